// round 1
// baseline (speedup 1.0000x reference)
#include <cuda_runtime.h>

#define DIM 8

// Closest point of D8 (integer vectors with even coordinate sum).
// Matches the JAX reference exactly:
//   f = round_half_even(x); d = x - f
//   worst = argmax(|d|)  (first occurrence on ties)
//   step  = (d >= 0) ? +1 : -1
//   if sum(f) odd: flip worst coord by step
__device__ __forceinline__ void closest_D8(const float x[DIM], float out[DIM]) {
    float f[DIM], d[DIM];
    int isum = 0;
#pragma unroll
    for (int i = 0; i < DIM; ++i) {
        f[i] = rintf(x[i]);           // round-half-to-even, same as jnp.round
        d[i] = x[i] - f[i];
        isum += __float2int_rn(f[i]); // exact: f[i] is integer-valued
    }
    int worst = 0;
    float best = fabsf(d[0]);
#pragma unroll
    for (int i = 1; i < DIM; ++i) {
        float ad = fabsf(d[i]);
        if (ad > best) { best = ad; worst = i; }  // strict > : first-occurrence tie-break
    }
    const bool odd = (isum & 1) != 0;
#pragma unroll
    for (int i = 0; i < DIM; ++i) {
        float step = (d[i] >= 0.0f) ? 1.0f : -1.0f;
        float g = f[i] + step;
        out[i] = (odd && (i == worst)) ? g : f[i];
    }
}

__global__ void __launch_bounds__(256)
e8_closest_kernel(const float* __restrict__ x, float* __restrict__ out, int n_rows) {
    int row = blockIdx.x * blockDim.x + threadIdx.x;
    if (row >= n_rows) return;

    // 32B per row: two coalesced float4 loads
    const float4* xin = reinterpret_cast<const float4*>(x) + 2 * (size_t)row;
    float4 a = xin[0];
    float4 b = xin[1];
    float v[DIM] = {a.x, a.y, a.z, a.w, b.x, b.y, b.z, b.w};

    // Coset 0: D8
    float c0[DIM];
    closest_D8(v, c0);

    // Coset 1: D8 + (1/2,...,1/2)
    float vs[DIM], c1[DIM];
#pragma unroll
    for (int i = 0; i < DIM; ++i) vs[i] = v[i] - 0.5f;
    closest_D8(vs, c1);
#pragma unroll
    for (int i = 0; i < DIM; ++i) c1[i] += 0.5f;

    // Pick nearer coset (d0 <= d1 -> c0, matching reference)
    float d0 = 0.0f, d1 = 0.0f;
#pragma unroll
    for (int i = 0; i < DIM; ++i) {
        float e0 = v[i] - c0[i];
        float e1 = v[i] - c1[i];
        d0 = fmaf(e0, e0, d0);
        d1 = fmaf(e1, e1, d1);
    }
    const bool take0 = (d0 <= d1);

    float r[DIM];
#pragma unroll
    for (int i = 0; i < DIM; ++i) r[i] = take0 ? c0[i] : c1[i];

    float4* o = reinterpret_cast<float4*>(out) + 2 * (size_t)row;
    o[0] = make_float4(r[0], r[1], r[2], r[3]);
    o[1] = make_float4(r[4], r[5], r[6], r[7]);
}

extern "C" void kernel_launch(void* const* d_in, const int* in_sizes, int n_in,
                              void* d_out, int out_size) {
    const float* x = (const float*)d_in[0];
    float* out = (float*)d_out;
    const int n_rows = in_sizes[0] / DIM;  // 4,000,000
    const int threads = 256;
    const int blocks = (n_rows + threads - 1) / threads;
    e8_closest_kernel<<<blocks, threads>>>(x, out, n_rows);
}